// round 1
// baseline (speedup 1.0000x reference)
#include <cuda_runtime.h>
#include <cuda_bf16.h>
#include <cstdint>

// Problem shape: A [64, 2048, 64], B [64, 64, 2048], out [64, 2048, 2048] (batch=4*16 flattened)
#define NBATCH 64
#define SDIM   2048
#define TDIM   2048
#define DDIM   64
#define NA_EL  (NBATCH * SDIM * DDIM)   // 8388608
#define NB_EL  (NBATCH * DDIM * TDIM)   // 8388608

// ---- device-global state (scratch; no allocations allowed) ----
__device__ float g_minA, g_maxA, g_minB, g_maxB;
__device__ float g_deltaA, g_zpA, g_deltaB, g_zpB, g_scale;
__device__ __nv_bfloat16 g_Aq[NA_EL];
__device__ __nv_bfloat16 g_Bq[NB_EL];

// ---- order-independent float atomic min/max (int-bit trick) ----
__device__ __forceinline__ void atomicMaxF(float* addr, float v) {
    if (v >= 0.0f) atomicMax((int*)addr, __float_as_int(v));
    else           atomicMin((unsigned int*)addr, (unsigned int)__float_as_int(v));
}
__device__ __forceinline__ void atomicMinF(float* addr, float v) {
    if (v >= 0.0f) atomicMin((int*)addr, __float_as_int(v));
    else           atomicMax((unsigned int*)addr, (unsigned int)__float_as_int(v));
}

__global__ void k_reset() {
    g_minA = 0.0f; g_maxA = 0.0f;
    g_minB = 0.0f; g_maxB = 0.0f;
}

// ---- pass 1: per-tensor min/max (init 0 matches min(.,0)/max(.,0) semantics) ----
__global__ void k_minmax(const float* __restrict__ x, int n4, int sel) {
    float vmin = 0.0f, vmax = 0.0f;
    const float4* x4 = (const float4*)x;
    for (int i = blockIdx.x * blockDim.x + threadIdx.x; i < n4;
         i += gridDim.x * blockDim.x) {
        float4 v = x4[i];
        vmin = fminf(vmin, fminf(fminf(v.x, v.y), fminf(v.z, v.w)));
        vmax = fmaxf(vmax, fmaxf(fmaxf(v.x, v.y), fmaxf(v.z, v.w)));
    }
    #pragma unroll
    for (int o = 16; o > 0; o >>= 1) {
        vmin = fminf(vmin, __shfl_xor_sync(0xffffffffu, vmin, o));
        vmax = fmaxf(vmax, __shfl_xor_sync(0xffffffffu, vmax, o));
    }
    __shared__ float smin[8], smax[8];
    int wid = threadIdx.x >> 5, lane = threadIdx.x & 31;
    if (lane == 0) { smin[wid] = vmin; smax[wid] = vmax; }
    __syncthreads();
    if (threadIdx.x == 0) {
        float m = smin[0], M = smax[0];
        #pragma unroll
        for (int w = 1; w < 8; w++) { m = fminf(m, smin[w]); M = fmaxf(M, smax[w]); }
        float* pmin = sel ? &g_minB : &g_minA;
        float* pmax = sel ? &g_maxB : &g_maxA;
        atomicMinF(pmin, m);
        atomicMaxF(pmax, M);
    }
}

// ---- pass 2: quant params (exact IEEE to match jnp) ----
__global__ void k_params() {
    float dA = __fdiv_rn(g_maxA - g_minA, 255.0f);
    dA = fmaxf(dA, 1e-8f);
    g_deltaA = dA;
    g_zpA = rintf(__fdiv_rn(-g_minA, dA));
    float dB = __fdiv_rn(g_maxB - g_minB, 255.0f);
    dB = fmaxf(dB, 1e-8f);
    g_deltaB = dB;
    g_zpB = rintf(__fdiv_rn(-g_minB, dB));
    g_scale = dA * dB;
}

// ---- pass 3: fake-quant to INTEGER-valued bf16 (exact: |q-zp| <= 255 < 2^8) ----
__global__ void k_quant(const float* __restrict__ x, int n4, int sel) {
    float delta = sel ? g_deltaB : g_deltaA;
    float zp    = sel ? g_zpB    : g_zpA;
    __nv_bfloat16* out = sel ? g_Bq : g_Aq;
    const float4* x4 = (const float4*)x;
    uint2* o2 = (uint2*)out;
    for (int i = blockIdx.x * blockDim.x + threadIdx.x; i < n4;
         i += gridDim.x * blockDim.x) {
        float4 v = x4[i];
        float q0 = fminf(fmaxf(rintf(__fdiv_rn(v.x, delta)) + zp, 0.0f), 255.0f) - zp;
        float q1 = fminf(fmaxf(rintf(__fdiv_rn(v.y, delta)) + zp, 0.0f), 255.0f) - zp;
        float q2 = fminf(fmaxf(rintf(__fdiv_rn(v.z, delta)) + zp, 0.0f), 255.0f) - zp;
        float q3 = fminf(fmaxf(rintf(__fdiv_rn(v.w, delta)) + zp, 0.0f), 255.0f) - zp;
        __nv_bfloat162 p0 = __floats2bfloat162_rn(q0, q1);
        __nv_bfloat162 p1 = __floats2bfloat162_rn(q2, q3);
        uint2 u;
        u.x = *(uint32_t*)&p0;
        u.y = *(uint32_t*)&p1;
        o2[i] = u;
    }
}

// ---- pass 4: batched GEMM, CTA tile 128x128, K=64 single load, mma.m16n8k16 ----
// grid (16 ntiles, 16 mtiles, 64 batches), 256 threads = 8 warps (2x4 warp grid)
__global__ void __launch_bounds__(256) k_gemm(float* __restrict__ out) {
    __shared__ __nv_bfloat16 sA[128][72];   // 64 cols + 8 pad (16B row shift -> no LDSM conflicts)
    __shared__ __nv_bfloat16 sB[64][136];   // 128 cols + 8 pad

    const int b  = blockIdx.z;
    const int m0 = blockIdx.y * 128;
    const int n0 = blockIdx.x * 128;
    const __nv_bfloat16* Ab = g_Aq + (size_t)b * SDIM * DDIM;
    const __nv_bfloat16* Bb = g_Bq + (size_t)b * DDIM * TDIM;
    float* ob = out + (size_t)b * SDIM * TDIM;
    const int tid = threadIdx.x;

    // load A tile: 128 rows x 64 cols = 1024 x 16B chunks
    #pragma unroll
    for (int it = 0; it < 4; it++) {
        int id = tid + it * 256;
        int r = id >> 3, c = (id & 7) * 8;
        *(uint4*)&sA[r][c] = *(const uint4*)(Ab + (m0 + r) * DDIM + c);
    }
    // load B tile: 64 rows x 128 cols = 1024 x 16B chunks
    #pragma unroll
    for (int it = 0; it < 4; it++) {
        int id = tid + it * 256;
        int r = id >> 4, c = (id & 15) * 8;
        *(uint4*)&sB[r][c] = *(const uint4*)(Bb + r * TDIM + n0 + c);
    }
    __syncthreads();

    const int warp = tid >> 5, lane = tid & 31;
    const int wm = warp >> 2;      // 0..1 -> 64 rows each
    const int wn = warp & 3;       // 0..3 -> 32 cols each

    float acc[4][4][4];
    #pragma unroll
    for (int mi = 0; mi < 4; mi++)
        #pragma unroll
        for (int ni = 0; ni < 4; ni++)
            #pragma unroll
            for (int q = 0; q < 4; q++) acc[mi][ni][q] = 0.0f;

    #pragma unroll
    for (int ks = 0; ks < 4; ks++) {
        const int k0 = ks * 16;
        // A fragments: 4 m-tiles of 16x16 via ldmatrix.x4
        uint32_t af[4][4];
        #pragma unroll
        for (int mi = 0; mi < 4; mi++) {
            int r = wm * 64 + mi * 16 + (lane & 15);
            int c = k0 + (lane >> 4) * 8;
            uint32_t addr = (uint32_t)__cvta_generic_to_shared(&sA[r][c]);
            asm volatile(
                "ldmatrix.sync.aligned.m8n8.x4.shared.b16 {%0,%1,%2,%3}, [%4];"
                : "=r"(af[mi][0]), "=r"(af[mi][1]), "=r"(af[mi][2]), "=r"(af[mi][3])
                : "r"(addr));
        }
        // B fragments: 2 x ldmatrix.x4.trans, each covers 2 n-tiles (16 cols)
        uint32_t bf[4][2];
        #pragma unroll
        for (int nj = 0; nj < 2; nj++) {
            int r = k0 + (lane & 7) + ((lane >> 3) & 1) * 8;
            int c = wn * 32 + nj * 16 + (lane >> 4) * 8;
            uint32_t addr = (uint32_t)__cvta_generic_to_shared(&sB[r][c]);
            uint32_t t0, t1, t2, t3;
            asm volatile(
                "ldmatrix.sync.aligned.m8n8.x4.trans.shared.b16 {%0,%1,%2,%3}, [%4];"
                : "=r"(t0), "=r"(t1), "=r"(t2), "=r"(t3)
                : "r"(addr));
            bf[nj * 2 + 0][0] = t0; bf[nj * 2 + 0][1] = t1;
            bf[nj * 2 + 1][0] = t2; bf[nj * 2 + 1][1] = t3;
        }
        #pragma unroll
        for (int mi = 0; mi < 4; mi++)
            #pragma unroll
            for (int ni = 0; ni < 4; ni++) {
                asm volatile(
                    "mma.sync.aligned.m16n8k16.row.col.f32.bf16.bf16.f32 "
                    "{%0,%1,%2,%3}, {%4,%5,%6,%7}, {%8,%9}, {%0,%1,%2,%3};"
                    : "+f"(acc[mi][ni][0]), "+f"(acc[mi][ni][1]),
                      "+f"(acc[mi][ni][2]), "+f"(acc[mi][ni][3])
                    : "r"(af[mi][0]), "r"(af[mi][1]), "r"(af[mi][2]), "r"(af[mi][3]),
                      "r"(bf[ni][0]), "r"(bf[ni][1]));
            }
    }

    const float s = g_scale;
    #pragma unroll
    for (int mi = 0; mi < 4; mi++) {
        #pragma unroll
        for (int ni = 0; ni < 4; ni++) {
            int r = m0 + wm * 64 + mi * 16 + (lane >> 2);
            int c = n0 + wn * 32 + ni * 8 + (lane & 3) * 2;
            float2 v0 = make_float2(acc[mi][ni][0] * s, acc[mi][ni][1] * s);
            float2 v1 = make_float2(acc[mi][ni][2] * s, acc[mi][ni][3] * s);
            *(float2*)&ob[(size_t)r * TDIM + c]       = v0;
            *(float2*)&ob[(size_t)(r + 8) * TDIM + c] = v1;
        }
    }
}

extern "C" void kernel_launch(void* const* d_in, const int* in_sizes, int n_in,
                              void* d_out, int out_size) {
    const float* A = (const float*)d_in[0];
    const float* B = (const float*)d_in[1];
    float* out = (float*)d_out;

    k_reset<<<1, 1>>>();
    k_minmax<<<512, 256>>>(A, NA_EL / 4, 0);
    k_minmax<<<512, 256>>>(B, NB_EL / 4, 1);
    k_params<<<1, 1>>>();
    k_quant<<<2048, 256>>>(A, NA_EL / 4, 0);
    k_quant<<<2048, 256>>>(B, NB_EL / 4, 1);
    k_gemm<<<dim3(16, 16, 64), 256>>>(out);
}